// round 6
// baseline (speedup 1.0000x reference)
#include <cuda_runtime.h>
#include <cuda_bf16.h>
#include <stdint.h>

// Problem constants (fixed by the dataset)
#define MAXN 50000
#define MAXE 500000
#define DIN  128

// ---------------- scratch (device globals; no allocation allowed) ----------------
// float4-accessed buffers get explicit 16B alignment (nvcc default is .align 4).
__device__ __align__(16) float g_Hs[(size_t)MAXN * 128];   // (X@W1)*dinv
__device__ __align__(16) float g_h1[(size_t)MAXN * 128];   // relu(layer1 out)
__device__ __align__(16) float g_Gs[(size_t)MAXN * 64];    // (h1@W2)*dinv
__device__ int   g_cnt[MAXN];                // in-degree (no self loop)
__device__ int   g_fill[MAXN];               // bucket fill cursors
__device__ int   g_rowptr[MAXN + 1];         // CSR row pointers (by dst)
__device__ int   g_srcs[MAXE];               // CSR column (src) indices
__device__ float g_dinv[MAXN];               // 1/sqrt(deg), deg = indeg+1
__device__ int   g_bsum[256];                // scan block sums
__device__ int   g_boff[256];                // scan block offsets

// ---------------- preprocessing ----------------
__global__ void k_init(int n) {
    int i = blockIdx.x * blockDim.x + threadIdx.x;
    if (i < n) { g_cnt[i] = 0; g_fill[i] = 0; }
}

// edge_index is int32 (JAX default config downgrades jnp.int64 -> int32)
__global__ void k_count(const int* __restrict__ ei, int E, int n) {
    int e = blockIdx.x * blockDim.x + threadIdx.x;
    if (e < E) {
        int d = ei[E + e];
        if ((unsigned)d < (unsigned)n)           // defensive: never form wild addresses
            atomicAdd(&g_cnt[d], 1);
    }
}

// exclusive scan, 512 elements per block
__global__ void k_scan1(int n) {
    __shared__ int sh[512];
    int i = blockIdx.x * 512 + threadIdx.x;
    int v = (i < n) ? g_cnt[i] : 0;
    sh[threadIdx.x] = v;
    __syncthreads();
    for (int off = 1; off < 512; off <<= 1) {
        int t = 0;
        if ((int)threadIdx.x >= off) t = sh[threadIdx.x - off];
        __syncthreads();
        sh[threadIdx.x] += t;
        __syncthreads();
    }
    int incl = sh[threadIdx.x];
    if (i < n) g_rowptr[i] = incl - v;       // block-local exclusive
    if (threadIdx.x == 511) g_bsum[blockIdx.x] = incl;
}

__global__ void k_scan2(int nb) {
    if (threadIdx.x == 0 && blockIdx.x == 0) {
        int run = 0;
        for (int b = 0; b < nb; b++) { g_boff[b] = run; run += g_bsum[b]; }
    }
}

__global__ void k_scan3(int n) {
    int i = blockIdx.x * blockDim.x + threadIdx.x;
    if (i < n) {
        int rp = g_rowptr[i] + g_boff[i >> 9];
        g_rowptr[i] = rp;
        g_dinv[i] = rsqrtf((float)(g_cnt[i] + 1));
        if (i == n - 1) g_rowptr[n] = rp + g_cnt[i];   // total valid edges
    }
}

__global__ void k_fill(const int* __restrict__ ei, int E, int n) {
    int e = blockIdx.x * blockDim.x + threadIdx.x;
    if (e < E) {
        int s = ei[e];
        int d = ei[E + e];
        if ((unsigned)s < (unsigned)n && (unsigned)d < (unsigned)n) {
            int pos = g_rowptr[d] + atomicAdd(&g_fill[d], 1);
            g_srcs[pos] = s;
        }
    }
}

// ---------------- GEMM: out[node][f] = (sum_k in[node][k] * W[k][f]) * dinv[node] ----------------
// LAYER==1: in = param (x), out = g_Hs ; LAYER==2: in = g_h1, out = g_Gs
template <int F, int LAYER>
__global__ void k_gemm(const float* __restrict__ Xin, const float* __restrict__ W, int n) {
    constexpr int CG = F / 8;          // column groups (8 cols each)
    constexpr int NG = 256 / CG;       // node groups (4 nodes each)
    constexpr int NB = NG * 4;         // nodes per block
    constexpr int KC = 32;             // k-chunk

    __shared__ float sW[KC][F];
    __shared__ float sX[NB][KC + 1];

    const float* __restrict__ in;
    float* __restrict__ out;
    if (LAYER == 1) { in = Xin;   out = g_Hs; }
    else            { in = g_h1;  out = g_Gs; }

    const int tid = threadIdx.x;
    const int cg  = tid % CG;
    const int ng  = tid / CG;
    const int node0 = blockIdx.x * NB;

    float acc[4][8];
    #pragma unroll
    for (int a = 0; a < 4; a++)
        #pragma unroll
        for (int b = 0; b < 8; b++) acc[a][b] = 0.f;

    for (int k0 = 0; k0 < DIN; k0 += KC) {
        // load W chunk (rows k0..k0+KC-1 are contiguous)
        {
            const float4* wsrc = (const float4*)(W + (size_t)k0 * F);
            float4* wdst = (float4*)&sW[0][0];
            for (int i = tid; i < KC * F / 4; i += 256) wdst[i] = wsrc[i];
        }
        // load X chunk [NB][KC]
        for (int i = tid; i < NB * KC / 4; i += 256) {
            int r = i / (KC / 4);
            int c = i % (KC / 4);
            int node = node0 + r;
            float4 v = make_float4(0.f, 0.f, 0.f, 0.f);
            if (node < n) v = *(const float4*)(in + (size_t)node * DIN + k0 + c * 4);
            sX[r][c * 4 + 0] = v.x;
            sX[r][c * 4 + 1] = v.y;
            sX[r][c * 4 + 2] = v.z;
            sX[r][c * 4 + 3] = v.w;
        }
        __syncthreads();

        #pragma unroll
        for (int k = 0; k < KC; k++) {
            const float4 wa = *(const float4*)&sW[k][cg * 8];
            const float4 wb = *(const float4*)&sW[k][cg * 8 + 4];
            #pragma unroll
            for (int ni = 0; ni < 4; ni++) {
                const float xv = sX[ng * 4 + ni][k];
                acc[ni][0] += xv * wa.x; acc[ni][1] += xv * wa.y;
                acc[ni][2] += xv * wa.z; acc[ni][3] += xv * wa.w;
                acc[ni][4] += xv * wb.x; acc[ni][5] += xv * wb.y;
                acc[ni][6] += xv * wb.z; acc[ni][7] += xv * wb.w;
            }
        }
        __syncthreads();
    }

    #pragma unroll
    for (int ni = 0; ni < 4; ni++) {
        int node = node0 + ng * 4 + ni;
        if (node < n) {
            float dv = g_dinv[node];
            float* o = out + (size_t)node * F + cg * 8;
            float4 o0 = make_float4(acc[ni][0] * dv, acc[ni][1] * dv, acc[ni][2] * dv, acc[ni][3] * dv);
            float4 o1 = make_float4(acc[ni][4] * dv, acc[ni][5] * dv, acc[ni][6] * dv, acc[ni][7] * dv);
            *(float4*)(o) = o0;
            *(float4*)(o + 4) = o1;
        }
    }
}

// ---------------- aggregation: out[i] = f( dinv[i]*(sum_e Hs[src] + Hs[i]) + b ) ----------------
// one warp per node; F=128 -> float4 per lane, F=64 -> float2 per lane.
// LAYER==1: in = g_Hs, out = g_h1 (relu) ; LAYER==2: in = g_Gs, out = param (no relu)
template <int F, int LAYER>
__global__ void k_agg(const float* __restrict__ bias, float* __restrict__ Yout, int n) {
    const int w = (blockIdx.x * blockDim.x + threadIdx.x) >> 5;
    const int lane = threadIdx.x & 31;
    if (w >= n) return;

    const int beg = g_rowptr[w];
    const int end = g_rowptr[w + 1];
    const float dv = g_dinv[w];

    if (F == 128) {
        const float4* __restrict__ H4 = (const float4*)g_Hs;
        float4 a = H4[(size_t)w * 32 + lane];   // self-loop term (Hs[i])
        int e = beg;
        for (; e + 3 < end; e += 4) {
            int s0 = g_srcs[e], s1 = g_srcs[e + 1], s2 = g_srcs[e + 2], s3 = g_srcs[e + 3];
            float4 v0 = H4[(size_t)s0 * 32 + lane];
            float4 v1 = H4[(size_t)s1 * 32 + lane];
            float4 v2 = H4[(size_t)s2 * 32 + lane];
            float4 v3 = H4[(size_t)s3 * 32 + lane];
            a.x += v0.x + v1.x + v2.x + v3.x;
            a.y += v0.y + v1.y + v2.y + v3.y;
            a.z += v0.z + v1.z + v2.z + v3.z;
            a.w += v0.w + v1.w + v2.w + v3.w;
        }
        for (; e < end; e++) {
            int s = g_srcs[e];
            float4 v = H4[(size_t)s * 32 + lane];
            a.x += v.x; a.y += v.y; a.z += v.z; a.w += v.w;
        }
        float4 bb = ((const float4*)bias)[lane];
        float4 o;
        o.x = fmaxf(a.x * dv + bb.x, 0.f);
        o.y = fmaxf(a.y * dv + bb.y, 0.f);
        o.z = fmaxf(a.z * dv + bb.z, 0.f);
        o.w = fmaxf(a.w * dv + bb.w, 0.f);
        ((float4*)g_h1)[(size_t)w * 32 + lane] = o;
    } else {
        const float2* __restrict__ H2 = (const float2*)g_Gs;
        float2 a = H2[(size_t)w * 32 + lane];   // self-loop term
        int e = beg;
        for (; e + 3 < end; e += 4) {
            int s0 = g_srcs[e], s1 = g_srcs[e + 1], s2 = g_srcs[e + 2], s3 = g_srcs[e + 3];
            float2 v0 = H2[(size_t)s0 * 32 + lane];
            float2 v1 = H2[(size_t)s1 * 32 + lane];
            float2 v2 = H2[(size_t)s2 * 32 + lane];
            float2 v3 = H2[(size_t)s3 * 32 + lane];
            a.x += v0.x + v1.x + v2.x + v3.x;
            a.y += v0.y + v1.y + v2.y + v3.y;
        }
        for (; e < end; e++) {
            int s = g_srcs[e];
            float2 v = H2[(size_t)s * 32 + lane];
            a.x += v.x; a.y += v.y;
        }
        float2 bb = ((const float2*)bias)[lane];
        float2 o;
        o.x = a.x * dv + bb.x;
        o.y = a.y * dv + bb.y;
        ((float2*)Yout)[(size_t)w * 32 + lane] = o;
    }
}

// ---------------- launch ----------------
extern "C" void kernel_launch(void* const* d_in, const int* in_sizes, int n_in,
                              void* d_out, int out_size) {
    const float* x  = (const float*)d_in[0];
    const int*   ei = (const int*)d_in[1];    // int32! (JAX x64 disabled)
    const float* W1 = (const float*)d_in[2];
    const float* b1 = (const float*)d_in[3];
    const float* W2 = (const float*)d_in[4];
    const float* b2 = (const float*)d_in[5];
    float*       out = (float*)d_out;

    const int n = in_sizes[0] / 128;   // 50000
    const int E = in_sizes[1] / 2;     // 500000
    const int nb = (n + 511) / 512;

    k_init<<<(n + 255) / 256, 256>>>(n);
    k_count<<<(E + 255) / 256, 256>>>(ei, E, n);
    k_scan1<<<nb, 512>>>(n);
    k_scan2<<<1, 32>>>(nb);
    k_scan3<<<(n + 255) / 256, 256>>>(n);
    k_fill<<<(E + 255) / 256, 256>>>(ei, E, n);

    // layer 1: Hs = (x@W1)*dinv ; h1 = relu(dinv*(gather + self) + b1)
    k_gemm<128, 1><<<(n + 63) / 64, 256>>>(x, W1, n);
    k_agg<128, 1><<<(n + 7) / 8, 256>>>(b1, nullptr, n);

    // layer 2: Gs = (h1@W2)*dinv ; out = dinv*(gather + self) + b2
    k_gemm<64, 2><<<(n + 127) / 128, 256>>>(nullptr, W2, n);
    k_agg<64, 2><<<(n + 7) / 8, 256>>>(b2, out, n);
}